// round 1
// baseline (speedup 1.0000x reference)
#include <cuda_runtime.h>
#include <math.h>

#define D_DIM 2048
#define EMB   256
#define E_EXP 64
#define MAX_N 65536

// Scratch (device-global arrays: allocation-free per harness rules)
__device__ float g_proj[(size_t)MAX_N * EMB];   // [N, 256] projection
__device__ float g_embn[EMB * E_EXP];           // normalized expert_emb [256, 64]

// ---------------------------------------------------------------------------
// Kernel 0: column-wise L2 normalization of expert_emb [EMB, E] over EMB axis
// One block per expert column e; 256 threads = one per k.
// ---------------------------------------------------------------------------
__global__ void embn_kernel(const float* __restrict__ emb) {
    __shared__ float red[EMB];
    int e = blockIdx.x;
    int t = threadIdx.x;
    float v = emb[(size_t)t * E_EXP + e];
    red[t] = v * v;
    __syncthreads();
    #pragma unroll
    for (int s = 128; s > 0; s >>= 1) {
        if (t < s) red[t] += red[t + s];
        __syncthreads();
    }
    float inv = 1.0f / sqrtf(red[0] + 1e-12f);
    g_embn[(size_t)t * E_EXP + e] = v * inv;
}

// ---------------------------------------------------------------------------
// Kernel 1: fp32 SGEMM  proj[M,256] = x[M,2048] @ W[2048,256]
// 128x128 CTA tile, BK=8, double-buffered SMEM, 4x4x(2x2) per-thread tile.
// ---------------------------------------------------------------------------
__global__ void __launch_bounds__(256, 2) sgemm_kernel(
        const float* __restrict__ A, const float* __restrict__ B, int M) {
    const int K = D_DIM;
    const int N = EMB;
    __shared__ float As[2][8][128];
    __shared__ float Bs[2][8][128];

    int bm = blockIdx.x * 128;
    int bn = blockIdx.y * 128;
    int tid = threadIdx.x;

    // A loader: 128 rows x 8 cols, one float4 per thread
    int arow = tid >> 1;
    int acol = (tid & 1) << 2;
    // B loader: 8 rows x 128 cols, one float4 per thread
    int brow = tid >> 5;
    int bcol = (tid & 31) << 2;

    const float* Ap = A + (size_t)(bm + arow) * K + acol;
    const float* Bp = B + (size_t)brow * N + bn + bcol;

    float4 a4 = *(const float4*)Ap;
    float4 b4 = *(const float4*)Bp;
    As[0][acol + 0][arow] = a4.x;
    As[0][acol + 1][arow] = a4.y;
    As[0][acol + 2][arow] = a4.z;
    As[0][acol + 3][arow] = a4.w;
    *(float4*)&Bs[0][brow][bcol] = b4;
    __syncthreads();

    int tx = tid & 15;
    int ty = tid >> 4;

    float acc[2][2][4][4];
    #pragma unroll
    for (int im = 0; im < 2; im++)
        #pragma unroll
        for (int in = 0; in < 2; in++)
            #pragma unroll
            for (int i = 0; i < 4; i++)
                #pragma unroll
                for (int j = 0; j < 4; j++)
                    acc[im][in][i][j] = 0.0f;

    const int NIT = K / 8;
    for (int kt = 0; kt < NIT; kt++) {
        int cur = kt & 1;
        int nxt = cur ^ 1;
        if (kt + 1 < NIT) {
            a4 = *(const float4*)(Ap + (kt + 1) * 8);
            b4 = *(const float4*)(Bp + (size_t)(kt + 1) * 8 * N);
        }
        #pragma unroll
        for (int k = 0; k < 8; k++) {
            float4 fa0 = *(const float4*)&As[cur][k][ty * 4];
            float4 fa1 = *(const float4*)&As[cur][k][64 + ty * 4];
            float4 fb0 = *(const float4*)&Bs[cur][k][tx * 4];
            float4 fb1 = *(const float4*)&Bs[cur][k][64 + tx * 4];
            float av[2][4] = {{fa0.x, fa0.y, fa0.z, fa0.w},
                              {fa1.x, fa1.y, fa1.z, fa1.w}};
            float bv[2][4] = {{fb0.x, fb0.y, fb0.z, fb0.w},
                              {fb1.x, fb1.y, fb1.z, fb1.w}};
            #pragma unroll
            for (int im = 0; im < 2; im++)
                #pragma unroll
                for (int in = 0; in < 2; in++)
                    #pragma unroll
                    for (int i = 0; i < 4; i++)
                        #pragma unroll
                        for (int j = 0; j < 4; j++)
                            acc[im][in][i][j] = fmaf(av[im][i], bv[in][j], acc[im][in][i][j]);
        }
        if (kt + 1 < NIT) {
            As[nxt][acol + 0][arow] = a4.x;
            As[nxt][acol + 1][arow] = a4.y;
            As[nxt][acol + 2][arow] = a4.z;
            As[nxt][acol + 3][arow] = a4.w;
            *(float4*)&Bs[nxt][brow][bcol] = b4;
        }
        __syncthreads();
    }

    // Write proj tile
    #pragma unroll
    for (int im = 0; im < 2; im++) {
        #pragma unroll
        for (int i = 0; i < 4; i++) {
            size_t row = (size_t)(bm + im * 64 + ty * 4 + i);
            #pragma unroll
            for (int in = 0; in < 2; in++) {
                float4 v = make_float4(acc[im][in][i][0], acc[im][in][i][1],
                                       acc[im][in][i][2], acc[im][in][i][3]);
                *(float4*)&g_proj[row * N + bn + in * 64 + tx * 4] = v;
            }
        }
    }
}

// ---------------------------------------------------------------------------
// Kernel 2: per-row gating epilogue.
// One warp per row: L2-normalize proj row, 64 cosine dots against SMEM emb_n
// (pair-interleaved: lane l covers experts l and l+32), top-2 (JAX tie-break:
// lowest index wins), masked softmax + raw softmax, write all 5 outputs.
// ---------------------------------------------------------------------------
__global__ void __launch_bounds__(256) gate_kernel(
        const float* __restrict__ tptr, float* __restrict__ out, int M) {
    extern __shared__ float sh[];
    float2* s_emb = (float2*)sh;                       // [256][32] pairs (e, e+32)
    int tid = threadIdx.x;
    int lane = tid & 31;
    int warp = tid >> 5;
    float* s_proj = sh + EMB * E_EXP + warp * EMB;     // 256 floats per warp

    // Fill pair-interleaved emb into SMEM
    for (int i = tid; i < EMB * 32; i += 256) {
        int k = i >> 5;
        int l = i & 31;
        s_emb[i] = make_float2(g_embn[k * 64 + l], g_embn[k * 64 + l + 32]);
    }
    __syncthreads();

    float temp = tptr[0];

    size_t nM = (size_t)M;
    float* out_ew  = out;                 // expert_weights [N,64]
    float* out_ti  = out + nM * 64;       // top_i          [N,2]
    float* out_lg  = out + nM * 66;       // logits         [N,64]
    float* out_cs  = out + nM * 130;      // cos            [N,64]
    float* out_raw = out + nM * 194;      // raw_gate_probs [N,64]

    int gw = blockIdx.x * 8 + warp;
    int nw = gridDim.x * 8;

    for (int r = gw; r < M; r += nw) {
        const float4* pr = (const float4*)(g_proj + (size_t)r * EMB);
        float4 v0 = pr[lane];
        float4 v1 = pr[lane + 32];
        float ss = v0.x * v0.x + v0.y * v0.y + v0.z * v0.z + v0.w * v0.w
                 + v1.x * v1.x + v1.y * v1.y + v1.z * v1.z + v1.w * v1.w;
        #pragma unroll
        for (int off = 16; off > 0; off >>= 1)
            ss += __shfl_xor_sync(0xffffffffu, ss, off);
        float inv = 1.0f / sqrtf(ss + 1e-12f);

        float4 n0 = make_float4(v0.x * inv, v0.y * inv, v0.z * inv, v0.w * inv);
        float4 n1 = make_float4(v1.x * inv, v1.y * inv, v1.z * inv, v1.w * inv);
        ((float4*)s_proj)[lane] = n0;
        ((float4*)s_proj)[lane + 32] = n1;
        __syncwarp();

        float c0 = 0.0f, c1 = 0.0f;
        #pragma unroll 8
        for (int k = 0; k < EMB; k++) {
            float pn = s_proj[k];
            float2 e2 = s_emb[k * 32 + lane];
            c0 = fmaf(pn, e2.x, c0);
            c1 = fmaf(pn, e2.y, c1);
        }
        __syncwarp();

        float l0 = c0 * temp;
        float l1 = c1 * temp;

        // top-1 (lowest index on ties, matching lax.top_k)
        float bv = l0; int bi = lane;
        if (l1 > bv) { bv = l1; bi = lane + 32; }
        #pragma unroll
        for (int off = 16; off > 0; off >>= 1) {
            float ov = __shfl_xor_sync(0xffffffffu, bv, off);
            int   oi = __shfl_xor_sync(0xffffffffu, bi, off);
            if (ov > bv || (ov == bv && oi < bi)) { bv = ov; bi = oi; }
        }
        float t1v = bv; int t1i = bi;

        // top-2: mask out top-1
        float m0 = (lane == t1i)      ? -INFINITY : l0;
        float m1 = (lane + 32 == t1i) ? -INFINITY : l1;
        bv = m0; bi = lane;
        if (m1 > bv || (m1 == bv && (lane + 32) < bi)) { bv = m1; bi = lane + 32; }
        #pragma unroll
        for (int off = 16; off > 0; off >>= 1) {
            float ov = __shfl_xor_sync(0xffffffffu, bv, off);
            int   oi = __shfl_xor_sync(0xffffffffu, bi, off);
            if (ov > bv || (ov == bv && oi < bi)) { bv = ov; bi = oi; }
        }
        float t2v = bv; int t2i = bi;

        // raw softmax over all 64 logits (max = t1v)
        float ex0 = expf(l0 - t1v);
        float ex1 = expf(l1 - t1v);
        float tot = ex0 + ex1;
        #pragma unroll
        for (int off = 16; off > 0; off >>= 1)
            tot += __shfl_xor_sync(0xffffffffu, tot, off);
        float r0 = ex0 / tot;
        float r1 = ex1 / tot;

        // masked softmax: only top-2 survive (exp(-1e9 - max) underflows to 0)
        float eT = expf(t2v - t1v);
        float denom = 1.0f + eT;
        float w1 = 1.0f / denom;
        float w2 = eT / denom;
        float ew0 = (lane == t1i) ? w1 : ((lane == t2i) ? w2 : 0.0f);
        float ew1 = (lane + 32 == t1i) ? w1 : ((lane + 32 == t2i) ? w2 : 0.0f);

        size_t ro = (size_t)r * 64;
        out_ew[ro + lane]       = ew0;
        out_ew[ro + lane + 32]  = ew1;
        out_lg[ro + lane]       = l0;
        out_lg[ro + lane + 32]  = l1;
        out_cs[ro + lane]       = c0;
        out_cs[ro + lane + 32]  = c1;
        out_raw[ro + lane]      = r0;
        out_raw[ro + lane + 32] = r1;
        if (lane == 0) {
            out_ti[(size_t)r * 2]     = (float)t1i;
            out_ti[(size_t)r * 2 + 1] = (float)t2i;
        }
    }
}

// ---------------------------------------------------------------------------
extern "C" void kernel_launch(void* const* d_in, const int* in_sizes, int n_in,
                              void* d_out, int out_size) {
    const float* x    = (const float*)d_in[0];   // [N, 2048]
    const float* W    = (const float*)d_in[1];   // [2048, 256]
    const float* emb  = (const float*)d_in[2];   // [256, 64]
    const float* temp = (const float*)d_in[3];   // [1]
    float* out = (float*)d_out;

    int M = in_sizes[0] / D_DIM;

    // 1) normalize expert embeddings
    embn_kernel<<<E_EXP, EMB>>>(emb);

    // 2) projection GEMM
    dim3 grid(M / 128, EMB / 128);
    sgemm_kernel<<<grid, 256>>>(x, W, M);

    // 3) fused gating epilogue
    int smem = (EMB * E_EXP + 8 * EMB) * (int)sizeof(float);  // 73728 B
    cudaFuncSetAttribute(gate_kernel, cudaFuncAttributeMaxDynamicSharedMemorySize, smem);
    gate_kernel<<<444, 256, smem>>>(temp, out, M);
}